// round 3
// baseline (speedup 1.0000x reference)
#include <cuda_runtime.h>
#include <cstdint>

namespace {
constexpr int kS = 2048;
constexpr int kD = 64;
constexpr int BM = 64;   // query rows per CTA (4 warps x 16)
constexpr int BN = 32;   // kv rows per iteration
constexpr int NW = 4;
constexpr int NT = 128;
constexpr int LDP = 36;  // padded smem row stride (floats) for P tiles

__device__ __forceinline__ float tf32f(float x) {
  uint32_t u;
  asm("cvt.rna.tf32.f32 %0, %1;" : "=r"(u) : "f"(x));
  return __uint_as_float(u);
}

__device__ __forceinline__ void mma8(float c[4], const uint32_t a[4],
                                     uint32_t b0, uint32_t b1) {
  asm volatile(
      "mma.sync.aligned.m16n8k8.row.col.f32.tf32.tf32.f32 "
      "{%0,%1,%2,%3}, {%4,%5,%6,%7}, {%8,%9}, {%0,%1,%2,%3};\n"
      : "+f"(c[0]), "+f"(c[1]), "+f"(c[2]), "+f"(c[3])
      : "r"(a[0]), "r"(a[1]), "r"(a[2]), "r"(a[3]), "r"(b0), "r"(b1));
}
}  // namespace

__global__ void __launch_bounds__(NT) attn_fwd(const float* __restrict__ Qg,
                                               const float* __restrict__ Kg,
                                               const float* __restrict__ Vg,
                                               float* __restrict__ Og) {
  const int bh = blockIdx.y;
  const int mBase = blockIdx.x * BM;
  const float* Qp = Qg + ((size_t)bh * kS + mBase) * kD;
  const float* Kp = Kg + (size_t)bh * kS * kD;
  const float* Vp = Vg + (size_t)bh * kS * kD;
  float* Op = Og + ((size_t)bh * kS + mBase) * kD;

  const int tid = threadIdx.x;
  const int w = tid >> 5;
  const int lane = tid & 31;
  const int gid = lane >> 2;  // groupID
  const int tig = lane & 3;   // thread-in-group

  // Fragment-major tiles: tile = 8x8 (hi,lo interleaved) = 32 lanes x float4.
  // K tiles: (nc 0..3, kc 0..7) -> id nc*8+kc.  V tiles: (dc 0..7, kc 0..3) -> id dc*4+kc.
  __shared__ __align__(16) float4 sK[32 * 32];  // 16 KB
  __shared__ __align__(16) float4 sV[32 * 32];  // 16 KB
  __shared__ __align__(16) float sP[NW * 16 * LDP];

  // ---- Q A-fragments straight from gmem (one time), split hi/lo
  uint32_t qhi[8][4], qlo[8][4];
  {
    const int r0 = w * 16 + gid;
#pragma unroll
    for (int kc = 0; kc < 8; ++kc) {
      int c = kc * 8 + tig;
      float x[4];
      x[0] = Qp[r0 * kD + c];
      x[1] = Qp[(r0 + 8) * kD + c];
      x[2] = Qp[r0 * kD + c + 4];
      x[3] = Qp[(r0 + 8) * kD + c + 4];
#pragma unroll
      for (int j = 0; j < 4; ++j) {
        float h = tf32f(x[j]);
        qhi[kc][j] = __float_as_uint(h);
        qlo[kc][j] = __float_as_uint(tf32f(x[j] - h));
      }
    }
  }

  float o[8][4];
#pragma unroll
  for (int dc = 0; dc < 8; ++dc)
#pragma unroll
    for (int j = 0; j < 4; ++j) o[dc][j] = 0.f;
  float m0 = -1e30f, m1 = -1e30f, l0 = 0.f, l1 = 0.f;

  float* sPw = sP + w * 16 * LDP;

  for (int t = 0; t < kS / BN; ++t) {
    const float* Kt = Kp + (size_t)t * BN * kD;
    const float* Vt = Vp + (size_t)t * BN * kD;

    // ---- produce fragment-major tiles; warp w owns tiles [w*8, w*8+8)
#pragma unroll
    for (int i = 0; i < 8; ++i) {
      {  // K tile
        int tk = w * 8 + i;
        int nc = tk >> 3, kc = tk & 7;
        int r = (nc * 8 + gid) * kD + kc * 8 + tig;
        float v0 = Kt[r];
        float v1 = Kt[r + 4];
        float h0 = tf32f(v0), h1 = tf32f(v1);
        sK[tk * 32 + lane] =
            make_float4(h0, tf32f(v0 - h0), h1, tf32f(v1 - h1));
      }
      {  // V tile
        int tv = w * 8 + i;
        int dc = tv >> 2, kc = tv & 3;
        int r = (kc * 8 + tig) * kD + dc * 8 + gid;
        float v0 = Vt[r];
        float v1 = Vt[r + 4 * kD];
        float h0 = tf32f(v0), h1 = tf32f(v1);
        sV[tv * 32 + lane] =
            make_float4(h0, tf32f(v0 - h0), h1, tf32f(v1 - h1));
      }
    }
    __syncthreads();

    // ---- S = Q K^T via 3xTF32; one LDS.128 per fragment triple
    float s[4][4];
#pragma unroll
    for (int nc = 0; nc < 4; ++nc)
#pragma unroll
      for (int j = 0; j < 4; ++j) s[nc][j] = 0.f;

#pragma unroll
    for (int nc = 0; nc < 4; ++nc) {
#pragma unroll
      for (int kc = 0; kc < 8; ++kc) {
        float4 f = sK[(nc * 8 + kc) * 32 + lane];
        uint32_t bh0 = __float_as_uint(f.x), bl0 = __float_as_uint(f.y);
        uint32_t bh1 = __float_as_uint(f.z), bl1 = __float_as_uint(f.w);
        mma8(s[nc], qhi[kc], bh0, bh1);
        mma8(s[nc], qlo[kc], bh0, bh1);
        mma8(s[nc], qhi[kc], bl0, bl1);
      }
    }

    // ---- online softmax (C-layout rows gid and gid+8)
    float rmax0 = s[0][0], rmax1 = s[0][2];
#pragma unroll
    for (int nc = 0; nc < 4; ++nc) {
      rmax0 = fmaxf(rmax0, fmaxf(s[nc][0], s[nc][1]));
      rmax1 = fmaxf(rmax1, fmaxf(s[nc][2], s[nc][3]));
    }
    rmax0 = fmaxf(rmax0, __shfl_xor_sync(0xffffffffu, rmax0, 1));
    rmax0 = fmaxf(rmax0, __shfl_xor_sync(0xffffffffu, rmax0, 2));
    rmax1 = fmaxf(rmax1, __shfl_xor_sync(0xffffffffu, rmax1, 1));
    rmax1 = fmaxf(rmax1, __shfl_xor_sync(0xffffffffu, rmax1, 2));
    float mn0 = fmaxf(m0, rmax0), mn1 = fmaxf(m1, rmax1);
    float a0 = __expf(m0 - mn0), a1 = __expf(m1 - mn1);
    m0 = mn0;
    m1 = mn1;
    float rs0 = 0.f, rs1 = 0.f;
#pragma unroll
    for (int nc = 0; nc < 4; ++nc) {
      s[nc][0] = __expf(s[nc][0] - m0);
      s[nc][1] = __expf(s[nc][1] - m0);
      s[nc][2] = __expf(s[nc][2] - m1);
      s[nc][3] = __expf(s[nc][3] - m1);
      rs0 += s[nc][0] + s[nc][1];
      rs1 += s[nc][2] + s[nc][3];
    }
    rs0 += __shfl_xor_sync(0xffffffffu, rs0, 1);
    rs0 += __shfl_xor_sync(0xffffffffu, rs0, 2);
    rs1 += __shfl_xor_sync(0xffffffffu, rs1, 1);
    rs1 += __shfl_xor_sync(0xffffffffu, rs1, 2);
    l0 = l0 * a0 + rs0;
    l1 = l1 * a1 + rs1;
#pragma unroll
    for (int dc = 0; dc < 8; ++dc) {
      o[dc][0] *= a0;
      o[dc][1] *= a0;
      o[dc][2] *= a1;
      o[dc][3] *= a1;
    }

    // ---- P: C-layout -> smem -> A-layout (per-warp private tile)
#pragma unroll
    for (int nc = 0; nc < 4; ++nc) {
      *(float2*)&sPw[gid * LDP + nc * 8 + 2 * tig] =
          make_float2(s[nc][0], s[nc][1]);
      *(float2*)&sPw[(gid + 8) * LDP + nc * 8 + 2 * tig] =
          make_float2(s[nc][2], s[nc][3]);
    }
    __syncwarp();

    uint32_t phi[4][4], plo[4][4];
#pragma unroll
    for (int kc = 0; kc < 4; ++kc) {
      int c = kc * 8 + tig;
      float x[4];
      x[0] = sPw[gid * LDP + c];
      x[1] = sPw[(gid + 8) * LDP + c];
      x[2] = sPw[gid * LDP + c + 4];
      x[3] = sPw[(gid + 8) * LDP + c + 4];
#pragma unroll
      for (int j = 0; j < 4; ++j) {
        float h = tf32f(x[j]);
        phi[kc][j] = __float_as_uint(h);
        plo[kc][j] = __float_as_uint(tf32f(x[j] - h));
      }
    }

    // ---- O += P V via 3xTF32; one LDS.128 per fragment triple
#pragma unroll
    for (int dc = 0; dc < 8; ++dc) {
#pragma unroll
      for (int kc = 0; kc < 4; ++kc) {
        float4 f = sV[(dc * 4 + kc) * 32 + lane];
        uint32_t bh0 = __float_as_uint(f.x), bl0 = __float_as_uint(f.y);
        uint32_t bh1 = __float_as_uint(f.z), bl1 = __float_as_uint(f.w);
        mma8(o[dc], phi[kc], bh0, bh1);
        mma8(o[dc], plo[kc], bh0, bh1);
        mma8(o[dc], phi[kc], bl0, bl1);
      }
    }
    __syncthreads();
  }

  // ---- epilogue: normalize and store
  const float inv0 = 1.f / l0, inv1 = 1.f / l1;
  const int r0 = w * 16 + gid;
#pragma unroll
  for (int dc = 0; dc < 8; ++dc) {
    int c = dc * 8 + 2 * tig;
    *(float2*)&Op[r0 * kD + c] = make_float2(o[dc][0] * inv0, o[dc][1] * inv0);
    *(float2*)&Op[(r0 + 8) * kD + c] =
        make_float2(o[dc][2] * inv1, o[dc][3] * inv1);
  }
}

extern "C" void kernel_launch(void* const* d_in, const int* in_sizes, int n_in,
                              void* d_out, int out_size) {
  const float* Q = (const float*)d_in[0];  // input_query
  const float* K = (const float*)d_in[1];  // input_key
  const float* V = (const float*)d_in[2];  // input_value
  float* O = (float*)d_out;
  dim3 grid(kS / BM, 4 * 16);  // 32 M-tiles x 64 (b,h)
  attn_fwd<<<grid, NT>>>(Q, K, V, O);
}

// round 8
// speedup vs baseline: 2.2708x; 2.2708x over previous
#include <cuda_runtime.h>
#include <cuda_bf16.h>
#include <cstdint>

namespace {
constexpr int kS = 2048;
constexpr int kD = 64;
constexpr int BM = 64;   // query rows per CTA (4 warps x 16)
constexpr int BN = 32;   // kv rows per iteration
constexpr int NT = 128;
constexpr int ITERS = kS / BN;

// smem: four bf16 tiles (Kh,Kl,Vh,Vl), each 32 rows x 64 bf16 = 128B rows.
constexpr int SM_KH = 0;
constexpr int SM_KL = SM_KH + BN * 128;
constexpr int SM_VH = SM_KL + BN * 128;
constexpr int SM_VL = SM_VH + BN * 128;
constexpr int SM_BYTES = SM_VL + BN * 128;  // 16 KB

__device__ __forceinline__ uint32_t smem_u32(const void* p) {
  uint32_t a;
  asm("{ .reg .u64 t; cvta.to.shared.u64 t, %1; cvt.u32.u64 %0, t; }"
      : "=r"(a) : "l"(p));
  return a;
}
__device__ __forceinline__ uint32_t pkbf(float a, float b) {
  __nv_bfloat162 t = __floats2bfloat162_rn(a, b);
  return *reinterpret_cast<uint32_t*>(&t);
}
__device__ __forceinline__ float lo_of(float x) {
  return x - __bfloat162float(__float2bfloat16(x));
}

__device__ __forceinline__ void mma16(float c[4], const uint32_t a[4],
                                      uint32_t b0, uint32_t b1) {
  asm volatile(
      "mma.sync.aligned.m16n8k16.row.col.f32.bf16.bf16.f32 "
      "{%0,%1,%2,%3}, {%4,%5,%6,%7}, {%8,%9}, {%0,%1,%2,%3};\n"
      : "+f"(c[0]), "+f"(c[1]), "+f"(c[2]), "+f"(c[3])
      : "r"(a[0]), "r"(a[1]), "r"(a[2]), "r"(a[3]), "r"(b0), "r"(b1));
}
__device__ __forceinline__ void ldsm4(uint32_t& r0, uint32_t& r1, uint32_t& r2,
                                      uint32_t& r3, uint32_t addr) {
  asm volatile(
      "ldmatrix.sync.aligned.m8n8.x4.shared.b16 {%0,%1,%2,%3}, [%4];"
      : "=r"(r0), "=r"(r1), "=r"(r2), "=r"(r3) : "r"(addr));
}
__device__ __forceinline__ void ldsm4t(uint32_t& r0, uint32_t& r1, uint32_t& r2,
                                       uint32_t& r3, uint32_t addr) {
  asm volatile(
      "ldmatrix.sync.aligned.m8n8.x4.trans.shared.b16 {%0,%1,%2,%3}, [%4];"
      : "=r"(r0), "=r"(r1), "=r"(r2), "=r"(r3) : "r"(addr));
}
}  // namespace

__global__ void __launch_bounds__(NT) attn_fwd(const float* __restrict__ Qg,
                                               const float* __restrict__ Kg,
                                               const float* __restrict__ Vg,
                                               float* __restrict__ Og) {
  const int bh = blockIdx.y;
  const int mBase = blockIdx.x * BM;
  const float* Qp = Qg + ((size_t)bh * kS + mBase) * kD;
  const float* Kp = Kg + (size_t)bh * kS * kD;
  const float* Vp = Vg + (size_t)bh * kS * kD;
  float* Op = Og + ((size_t)bh * kS + mBase) * kD;

  const int tid = threadIdx.x;
  const int w = tid >> 5;
  const int lane = tid & 31;
  const int gid = lane >> 2;
  const int tig = lane & 3;

  __shared__ __align__(1024) char smc[SM_BYTES];
  const uint32_t sbase = smem_u32(smc);

  // ---- Q A-fragments (bf16 hi/lo), straight from gmem, one time.
  // m16n8k16 A layout: a0=(gid, k0,k0+1) a1=(gid+8,..) a2=(gid, k0+8..) a3=(gid+8,k0+8..)
  uint32_t qh[4][4], ql[4][4];
  {
    const int r0 = w * 16 + gid;
#pragma unroll
    for (int kc = 0; kc < 4; ++kc) {
      int c = kc * 16 + 2 * tig;
      float2 x0 = *(const float2*)&Qp[r0 * kD + c];
      float2 x1 = *(const float2*)&Qp[(r0 + 8) * kD + c];
      float2 x2 = *(const float2*)&Qp[r0 * kD + c + 8];
      float2 x3 = *(const float2*)&Qp[(r0 + 8) * kD + c + 8];
      qh[kc][0] = pkbf(x0.x, x0.y);
      qh[kc][1] = pkbf(x1.x, x1.y);
      qh[kc][2] = pkbf(x2.x, x2.y);
      qh[kc][3] = pkbf(x3.x, x3.y);
      ql[kc][0] = pkbf(lo_of(x0.x), lo_of(x0.y));
      ql[kc][1] = pkbf(lo_of(x1.x), lo_of(x1.y));
      ql[kc][2] = pkbf(lo_of(x2.x), lo_of(x2.y));
      ql[kc][3] = pkbf(lo_of(x3.x), lo_of(x3.y));
    }
  }

  // ---- per-lane ldmatrix address invariants
  // K (no trans): lanes 0-15 -> hi tile (two k-halves), 16-31 -> lo tile.
  const uint32_t xor16 = (lane & 7) << 4;
  const uint32_t khalf = ((lane >> 3) & 1) * 16;
  const uint32_t kbase =
      sbase + ((lane >> 4) ? SM_KL : SM_KH) + (lane & 7) * 128;
  // V (trans): lanes per 8 = one 8x8; sel bit0 -> key block +8, bit1 -> lo tile
  const uint32_t vrow = (lane & 7) + ((lane >> 3) & 1) * 8;
  const uint32_t vbase =
      sbase + ((lane >> 4) ? SM_VL : SM_VH) + vrow * 128;

  float o[8][4];
#pragma unroll
  for (int dc = 0; dc < 8; ++dc)
#pragma unroll
    for (int j = 0; j < 4; ++j) o[dc][j] = 0.f;
  float m0 = -1e30f, m1 = -1e30f, l0 = 0.f, l1 = 0.f;

  // ---- software pipeline: tile t in regs while computing t-1
  float4 kr[4], vr[4];
  {
    const float4* K4 = reinterpret_cast<const float4*>(Kp);
    const float4* V4 = reinterpret_cast<const float4*>(Vp);
#pragma unroll
    for (int i = 0; i < 4; ++i) {
      kr[i] = K4[i * NT + tid];
      vr[i] = V4[i * NT + tid];
    }
  }

  for (int t = 0; t < ITERS; ++t) {
    // ---- store current tile (bf16 hi/lo, swizzled 128B rows)
#pragma unroll
    for (int i = 0; i < 4; ++i) {
      int f = i * NT + tid;
      int r = f >> 4, c4 = f & 15;
      int so = r * 128 + ((c4 * 8) ^ ((r & 7) << 4));
      float4 x = kr[i];
      *(uint2*)(smc + SM_KH + so) = make_uint2(pkbf(x.x, x.y), pkbf(x.z, x.w));
      *(uint2*)(smc + SM_KL + so) = make_uint2(
          pkbf(lo_of(x.x), lo_of(x.y)), pkbf(lo_of(x.z), lo_of(x.w)));
      float4 y = vr[i];
      *(uint2*)(smc + SM_VH + so) = make_uint2(pkbf(y.x, y.y), pkbf(y.z, y.w));
      *(uint2*)(smc + SM_VL + so) = make_uint2(
          pkbf(lo_of(y.x), lo_of(y.y)), pkbf(lo_of(y.z), lo_of(y.w)));
    }
    __syncthreads();

    // ---- prefetch next tile (overlaps with compute below)
    if (t + 1 < ITERS) {
      const float4* K4 =
          reinterpret_cast<const float4*>(Kp + (size_t)(t + 1) * BN * kD);
      const float4* V4 =
          reinterpret_cast<const float4*>(Vp + (size_t)(t + 1) * BN * kD);
#pragma unroll
      for (int i = 0; i < 4; ++i) {
        kr[i] = K4[i * NT + tid];
        vr[i] = V4[i * NT + tid];
      }
    }

    // ---- S = Q K^T : 3 bf16 products, B via one ldmatrix.x4 per triple
    float s[4][4];
#pragma unroll
    for (int nc = 0; nc < 4; ++nc)
#pragma unroll
      for (int j = 0; j < 4; ++j) s[nc][j] = 0.f;

#pragma unroll
    for (int nc = 0; nc < 4; ++nc) {
#pragma unroll
      for (int kc = 0; kc < 4; ++kc) {
        uint32_t bh0, bh1, bl0, bl1;
        ldsm4(bh0, bh1, bl0, bl1,
              kbase + nc * 1024 + ((kc * 32 + khalf) ^ xor16));
        mma16(s[nc], qh[kc], bh0, bh1);
        mma16(s[nc], ql[kc], bh0, bh1);
        mma16(s[nc], qh[kc], bl0, bl1);
      }
    }

    // ---- online softmax (rows gid, gid+8)
    float rmax0 = s[0][0], rmax1 = s[0][2];
#pragma unroll
    for (int nc = 0; nc < 4; ++nc) {
      rmax0 = fmaxf(rmax0, fmaxf(s[nc][0], s[nc][1]));
      rmax1 = fmaxf(rmax1, fmaxf(s[nc][2], s[nc][3]));
    }
    rmax0 = fmaxf(rmax0, __shfl_xor_sync(0xffffffffu, rmax0, 1));
    rmax0 = fmaxf(rmax0, __shfl_xor_sync(0xffffffffu, rmax0, 2));
    rmax1 = fmaxf(rmax1, __shfl_xor_sync(0xffffffffu, rmax1, 1));
    rmax1 = fmaxf(rmax1, __shfl_xor_sync(0xffffffffu, rmax1, 2));
    float mn0 = fmaxf(m0, rmax0), mn1 = fmaxf(m1, rmax1);
    float a0 = __expf(m0 - mn0), a1 = __expf(m1 - mn1);
    m0 = mn0;
    m1 = mn1;
    float rs0 = 0.f, rs1 = 0.f;
#pragma unroll
    for (int nc = 0; nc < 4; ++nc) {
      s[nc][0] = __expf(s[nc][0] - m0);
      s[nc][1] = __expf(s[nc][1] - m0);
      s[nc][2] = __expf(s[nc][2] - m1);
      s[nc][3] = __expf(s[nc][3] - m1);
      rs0 += s[nc][0] + s[nc][1];
      rs1 += s[nc][2] + s[nc][3];
    }
    rs0 += __shfl_xor_sync(0xffffffffu, rs0, 1);
    rs0 += __shfl_xor_sync(0xffffffffu, rs0, 2);
    rs1 += __shfl_xor_sync(0xffffffffu, rs1, 1);
    rs1 += __shfl_xor_sync(0xffffffffu, rs1, 2);
    l0 = l0 * a0 + rs0;
    l1 = l1 * a1 + rs1;
#pragma unroll
    for (int dc = 0; dc < 8; ++dc) {
      o[dc][0] *= a0;
      o[dc][1] *= a0;
      o[dc][2] *= a1;
      o[dc][3] *= a1;
    }

    // ---- P A-fragments directly from C-fragments (no smem round trip)
    uint32_t phi[2][4], plo[2][4];
#pragma unroll
    for (int kk = 0; kk < 2; ++kk) {
      const float* sa = s[2 * kk];
      const float* sb = s[2 * kk + 1];
      phi[kk][0] = pkbf(sa[0], sa[1]);
      phi[kk][1] = pkbf(sa[2], sa[3]);
      phi[kk][2] = pkbf(sb[0], sb[1]);
      phi[kk][3] = pkbf(sb[2], sb[3]);
      plo[kk][0] = pkbf(lo_of(sa[0]), lo_of(sa[1]));
      plo[kk][1] = pkbf(lo_of(sa[2]), lo_of(sa[3]));
      plo[kk][2] = pkbf(lo_of(sb[0]), lo_of(sb[1]));
      plo[kk][3] = pkbf(lo_of(sb[2]), lo_of(sb[3]));
    }

    // ---- O += P V : B via ldmatrix.x4.trans (V natural layout)
#pragma unroll
    for (int dc = 0; dc < 8; ++dc) {
#pragma unroll
      for (int kk = 0; kk < 2; ++kk) {
        uint32_t bh0, bh1, bl0, bl1;
        ldsm4t(bh0, bh1, bl0, bl1,
               vbase + kk * 16 * 128 + ((dc * 16) ^ xor16));
        mma16(o[dc], phi[kk], bh0, bh1);
        mma16(o[dc], plo[kk], bh0, bh1);
        mma16(o[dc], phi[kk], bl0, bl1);
      }
    }
    __syncthreads();
  }

  // ---- epilogue
  const float inv0 = 1.f / l0, inv1 = 1.f / l1;
  const int r0 = w * 16 + gid;
#pragma unroll
  for (int dc = 0; dc < 8; ++dc) {
    int c = dc * 8 + 2 * tig;
    *(float2*)&Op[r0 * kD + c] = make_float2(o[dc][0] * inv0, o[dc][1] * inv0);
    *(float2*)&Op[(r0 + 8) * kD + c] =
        make_float2(o[dc][2] * inv1, o[dc][3] * inv1);
  }
}

extern "C" void kernel_launch(void* const* d_in, const int* in_sizes, int n_in,
                              void* d_out, int out_size) {
  const float* Q = (const float*)d_in[0];  // input_query
  const float* K = (const float*)d_in[1];  // input_key
  const float* V = (const float*)d_in[2];  // input_value
  float* O = (float*)d_out;
  dim3 grid(kS / BM, 4 * 16);  // 32 M-tiles x 64 (b,h)
  attn_fwd<<<grid, NT>>>(Q, K, V, O);
}

// round 9
// speedup vs baseline: 2.4535x; 1.0805x over previous
#include <cuda_runtime.h>
#include <cuda_bf16.h>
#include <cstdint>

namespace {
constexpr int kS = 2048;
constexpr int kD = 64;
constexpr int BM = 64;   // query rows per CTA (4 warps x 16)
constexpr int BN = 32;   // kv rows per iteration
constexpr int NT = 128;
constexpr int ITERS = kS / BN;

// smem: four bf16 tiles (Kh,Kl,Vh,Vl), each 32 rows x 64 bf16 = 128B rows.
constexpr int SM_KH = 0;
constexpr int SM_KL = SM_KH + BN * 128;
constexpr int SM_VH = SM_KL + BN * 128;
constexpr int SM_VL = SM_VH + BN * 128;
constexpr int SM_BYTES = SM_VL + BN * 128;  // 16 KB

__device__ __forceinline__ uint32_t smem_u32(const void* p) {
  uint32_t a;
  asm("{ .reg .u64 t; cvta.to.shared.u64 t, %1; cvt.u32.u64 %0, t; }"
      : "=r"(a) : "l"(p));
  return a;
}
__device__ __forceinline__ uint32_t pkbf(float a, float b) {
  __nv_bfloat162 t = __floats2bfloat162_rn(a, b);
  return *reinterpret_cast<uint32_t*>(&t);
}
__device__ __forceinline__ float lo_of(float x) {
  return x - __bfloat162float(__float2bfloat16(x));
}

__device__ __forceinline__ void mma16(float c[4], const uint32_t a[4],
                                      uint32_t b0, uint32_t b1) {
  asm volatile(
      "mma.sync.aligned.m16n8k16.row.col.f32.bf16.bf16.f32 "
      "{%0,%1,%2,%3}, {%4,%5,%6,%7}, {%8,%9}, {%0,%1,%2,%3};\n"
      : "+f"(c[0]), "+f"(c[1]), "+f"(c[2]), "+f"(c[3])
      : "r"(a[0]), "r"(a[1]), "r"(a[2]), "r"(a[3]), "r"(b0), "r"(b1));
}
__device__ __forceinline__ void ldsm4(uint32_t& r0, uint32_t& r1, uint32_t& r2,
                                      uint32_t& r3, uint32_t addr) {
  asm volatile(
      "ldmatrix.sync.aligned.m8n8.x4.shared.b16 {%0,%1,%2,%3}, [%4];"
      : "=r"(r0), "=r"(r1), "=r"(r2), "=r"(r3) : "r"(addr));
}
__device__ __forceinline__ void ldsm4t(uint32_t& r0, uint32_t& r1, uint32_t& r2,
                                       uint32_t& r3, uint32_t addr) {
  asm volatile(
      "ldmatrix.sync.aligned.m8n8.x4.trans.shared.b16 {%0,%1,%2,%3}, [%4];"
      : "=r"(r0), "=r"(r1), "=r"(r2), "=r"(r3) : "r"(addr));
}
}  // namespace

__global__ void __launch_bounds__(NT, 3)
attn_fwd(const float* __restrict__ Qg, const float* __restrict__ Kg,
         const float* __restrict__ Vg, float* __restrict__ Og) {
  const int bh = blockIdx.y;
  const int mBase = blockIdx.x * BM;
  const float* Qp = Qg + ((size_t)bh * kS + mBase) * kD;
  const float* Kp = Kg + (size_t)bh * kS * kD;
  const float* Vp = Vg + (size_t)bh * kS * kD;
  float* Op = Og + ((size_t)bh * kS + mBase) * kD;

  const int tid = threadIdx.x;
  const int w = tid >> 5;
  const int lane = tid & 31;
  const int gid = lane >> 2;
  const int tig = lane & 3;

  __shared__ __align__(1024) char smc[SM_BYTES];
  const uint32_t sbase = smem_u32(smc);

  // ---- Q A-fragments (bf16 hi/lo), straight from gmem, one time.
  uint32_t qh[4][4], ql[4][4];
  {
    const int r0 = w * 16 + gid;
#pragma unroll
    for (int kc = 0; kc < 4; ++kc) {
      int c = kc * 16 + 2 * tig;
      float2 x0 = *(const float2*)&Qp[r0 * kD + c];
      float2 x1 = *(const float2*)&Qp[(r0 + 8) * kD + c];
      float2 x2 = *(const float2*)&Qp[r0 * kD + c + 8];
      float2 x3 = *(const float2*)&Qp[(r0 + 8) * kD + c + 8];
      qh[kc][0] = pkbf(x0.x, x0.y);
      qh[kc][1] = pkbf(x1.x, x1.y);
      qh[kc][2] = pkbf(x2.x, x2.y);
      qh[kc][3] = pkbf(x3.x, x3.y);
      ql[kc][0] = pkbf(lo_of(x0.x), lo_of(x0.y));
      ql[kc][1] = pkbf(lo_of(x1.x), lo_of(x1.y));
      ql[kc][2] = pkbf(lo_of(x2.x), lo_of(x2.y));
      ql[kc][3] = pkbf(lo_of(x3.x), lo_of(x3.y));
    }
  }

  // ---- per-lane ldmatrix address invariants
  const uint32_t xor16 = (lane & 7) << 4;
  const uint32_t khalf = ((lane >> 3) & 1) * 16;
  const uint32_t kbase =
      sbase + ((lane >> 4) ? SM_KL : SM_KH) + (lane & 7) * 128;
  const uint32_t vrow = (lane & 7) + ((lane >> 3) & 1) * 8;
  const uint32_t vbase =
      sbase + ((lane >> 4) ? SM_VL : SM_VH) + vrow * 128;

  float o[8][4];
#pragma unroll
  for (int dc = 0; dc < 8; ++dc)
#pragma unroll
    for (int j = 0; j < 4; ++j) o[dc][j] = 0.f;
  float m0 = -1e30f, m1 = -1e30f, l0 = 0.f, l1 = 0.f;

  // ---- half-tile register prefetch (i=0,1); i=2,3 LDG'd in store phase
  float4 kr[2], vr[2];
  {
    const float4* K4 = reinterpret_cast<const float4*>(Kp);
    const float4* V4 = reinterpret_cast<const float4*>(Vp);
#pragma unroll
    for (int i = 0; i < 2; ++i) {
      kr[i] = K4[i * NT + tid];
      vr[i] = V4[i * NT + tid];
    }
  }

  for (int t = 0; t < ITERS; ++t) {
    const float4* K4t =
        reinterpret_cast<const float4*>(Kp + (size_t)t * BN * kD);
    const float4* V4t =
        reinterpret_cast<const float4*>(Vp + (size_t)t * BN * kD);
    // ---- store current tile (bf16 hi/lo, swizzled 128B rows)
#pragma unroll
    for (int i = 0; i < 4; ++i) {
      float4 x = (i < 2) ? kr[i] : K4t[i * NT + tid];
      float4 y = (i < 2) ? vr[i] : V4t[i * NT + tid];
      int f = i * NT + tid;
      int r = f >> 4, c4 = f & 15;
      int so = r * 128 + ((c4 * 8) ^ ((r & 7) << 4));
      *(uint2*)(smc + SM_KH + so) = make_uint2(pkbf(x.x, x.y), pkbf(x.z, x.w));
      *(uint2*)(smc + SM_KL + so) = make_uint2(
          pkbf(lo_of(x.x), lo_of(x.y)), pkbf(lo_of(x.z), lo_of(x.w)));
      *(uint2*)(smc + SM_VH + so) = make_uint2(pkbf(y.x, y.y), pkbf(y.z, y.w));
      *(uint2*)(smc + SM_VL + so) = make_uint2(
          pkbf(lo_of(y.x), lo_of(y.y)), pkbf(lo_of(y.z), lo_of(y.w)));
    }
    __syncthreads();

    // ---- prefetch first half of next tile (overlaps with compute below)
    if (t + 1 < ITERS) {
      const float4* K4 =
          reinterpret_cast<const float4*>(Kp + (size_t)(t + 1) * BN * kD);
      const float4* V4 =
          reinterpret_cast<const float4*>(Vp + (size_t)(t + 1) * BN * kD);
#pragma unroll
      for (int i = 0; i < 2; ++i) {
        kr[i] = K4[i * NT + tid];
        vr[i] = V4[i * NT + tid];
      }
    }

    // ---- S = Q K^T : 3 bf16 products, B via one ldmatrix.x4 per triple
    float s[4][4];
#pragma unroll
    for (int nc = 0; nc < 4; ++nc)
#pragma unroll
      for (int j = 0; j < 4; ++j) s[nc][j] = 0.f;

#pragma unroll
    for (int nc = 0; nc < 4; ++nc) {
#pragma unroll
      for (int kc = 0; kc < 4; ++kc) {
        uint32_t bh0, bh1, bl0, bl1;
        ldsm4(bh0, bh1, bl0, bl1,
              kbase + nc * 1024 + ((kc * 32 + khalf) ^ xor16));
        mma16(s[nc], qh[kc], bh0, bh1);
        mma16(s[nc], ql[kc], bh0, bh1);
        mma16(s[nc], qh[kc], bl0, bl1);
      }
    }

    // ---- online softmax (rows gid, gid+8)
    float rmax0 = s[0][0], rmax1 = s[0][2];
#pragma unroll
    for (int nc = 0; nc < 4; ++nc) {
      rmax0 = fmaxf(rmax0, fmaxf(s[nc][0], s[nc][1]));
      rmax1 = fmaxf(rmax1, fmaxf(s[nc][2], s[nc][3]));
    }
    rmax0 = fmaxf(rmax0, __shfl_xor_sync(0xffffffffu, rmax0, 1));
    rmax0 = fmaxf(rmax0, __shfl_xor_sync(0xffffffffu, rmax0, 2));
    rmax1 = fmaxf(rmax1, __shfl_xor_sync(0xffffffffu, rmax1, 1));
    rmax1 = fmaxf(rmax1, __shfl_xor_sync(0xffffffffu, rmax1, 2));
    float mn0 = fmaxf(m0, rmax0), mn1 = fmaxf(m1, rmax1);
    float a0 = __expf(m0 - mn0), a1 = __expf(m1 - mn1);
    m0 = mn0;
    m1 = mn1;
    float rs0 = 0.f, rs1 = 0.f;
#pragma unroll
    for (int nc = 0; nc < 4; ++nc) {
      s[nc][0] = __expf(s[nc][0] - m0);
      s[nc][1] = __expf(s[nc][1] - m0);
      s[nc][2] = __expf(s[nc][2] - m1);
      s[nc][3] = __expf(s[nc][3] - m1);
      rs0 += s[nc][0] + s[nc][1];
      rs1 += s[nc][2] + s[nc][3];
    }
    rs0 += __shfl_xor_sync(0xffffffffu, rs0, 1);
    rs0 += __shfl_xor_sync(0xffffffffu, rs0, 2);
    rs1 += __shfl_xor_sync(0xffffffffu, rs1, 1);
    rs1 += __shfl_xor_sync(0xffffffffu, rs1, 2);
    l0 = l0 * a0 + rs0;
    l1 = l1 * a1 + rs1;
#pragma unroll
    for (int dc = 0; dc < 8; ++dc) {
      o[dc][0] *= a0;
      o[dc][1] *= a0;
      o[dc][2] *= a1;
      o[dc][3] *= a1;
    }

    // ---- P A-fragments directly from C-fragments (no smem round trip)
    uint32_t phi[2][4], plo[2][4];
#pragma unroll
    for (int kk = 0; kk < 2; ++kk) {
      const float* sa = s[2 * kk];
      const float* sb = s[2 * kk + 1];
      phi[kk][0] = pkbf(sa[0], sa[1]);
      phi[kk][1] = pkbf(sa[2], sa[3]);
      phi[kk][2] = pkbf(sb[0], sb[1]);
      phi[kk][3] = pkbf(sb[2], sb[3]);
      plo[kk][0] = pkbf(lo_of(sa[0]), lo_of(sa[1]));
      plo[kk][1] = pkbf(lo_of(sa[2]), lo_of(sa[3]));
      plo[kk][2] = pkbf(lo_of(sb[0]), lo_of(sb[1]));
      plo[kk][3] = pkbf(lo_of(sb[2]), lo_of(sb[3]));
    }

    // ---- O += P V : B via ldmatrix.x4.trans (V natural layout)
#pragma unroll
    for (int dc = 0; dc < 8; ++dc) {
#pragma unroll
      for (int kk = 0; kk < 2; ++kk) {
        uint32_t bh0, bh1, bl0, bl1;
        ldsm4t(bh0, bh1, bl0, bl1,
               vbase + kk * 16 * 128 + ((dc * 16) ^ xor16));
        mma16(o[dc], phi[kk], bh0, bh1);
        mma16(o[dc], plo[kk], bh0, bh1);
        mma16(o[dc], phi[kk], bl0, bl1);
      }
    }
    __syncthreads();
  }

  // ---- epilogue
  const float inv0 = 1.f / l0, inv1 = 1.f / l1;
  const int r0 = w * 16 + gid;
#pragma unroll
  for (int dc = 0; dc < 8; ++dc) {
    int c = dc * 8 + 2 * tig;
    *(float2*)&Op[r0 * kD + c] = make_float2(o[dc][0] * inv0, o[dc][1] * inv0);
    *(float2*)&Op[(r0 + 8) * kD + c] =
        make_float2(o[dc][2] * inv1, o[dc][3] * inv1);
  }
}

extern "C" void kernel_launch(void* const* d_in, const int* in_sizes, int n_in,
                              void* d_out, int out_size) {
  const float* Q = (const float*)d_in[0];  // input_query
  const float* K = (const float*)d_in[1];  // input_key
  const float* V = (const float*)d_in[2];  // input_value
  float* O = (float*)d_out;
  dim3 grid(kS / BM, 4 * 16);  // 32 M-tiles x 64 (b,h)
  attn_fwd<<<grid, NT>>>(Q, K, V, O);
}